// round 8
// baseline (speedup 1.0000x reference)
#include <cuda_runtime.h>
#include <stdint.h>

#define N_TOK_TOTAL 16384
#define DPROJ 1024
#define EMB_SCALE 32.0f

// ---------------- device scratch (no allocations allowed) ----------------
__device__ int g_count[4];
__device__ int g_list[4][N_TOK_TOTAL];   // flat token index (output row)
__device__ int g_row[4][N_TOK_TOTAL];    // local embedding row

__global__ void reset_kernel() {
    if (threadIdx.x < 4) g_count[threadIdx.x] = 0;
}

__global__ void partition_kernel(const int* __restrict__ inp) {
    int t = blockIdx.x * blockDim.x + threadIdx.x;
    if (t >= N_TOK_TOTAL) return;
    int idx = inp[t];
    int c, l;
    if (idx < 20000)      { c = 0; l = 0; }
    else if (idx < 40000) { c = 1; l = 20000; }
    else if (idx < 200000){ c = 2; l = 40000; }
    else                  { c = 3; l = 200000; }
    int pos = atomicAdd(&g_count[c], 1);
    g_list[c][pos] = t;
    g_row[c][pos]  = idx - l;
}

__device__ __forceinline__ uint32_t f2tf32(float f) {
    uint32_t u;
    asm("cvt.rna.tf32.f32 %0, %1;" : "=r"(u) : "f"(f));
    return u;
}

// ---------------- fused tf32 mma.sync GEMM, cp.async double-buffered -------
// grid: (m-tile[128], n-tile[128], cluster). Early-exit on dynamic counts.
// D[m, n] = sum_k A[m, k] * B[n, k]; A = gathered emb rows, B = proj rows.
// 8 warps in 4(M) x 2(N); each warp 32x64 via m16n8k8 tf32 frags.
// cp.async GMEM->smem (raw fp32), consumer-side cvt.rna.tf32.
__global__ __launch_bounds__(256, 2)
void fused_gemm_tc(const float* __restrict__ e0, const float* __restrict__ e1,
                   const float* __restrict__ e2, const float* __restrict__ e3,
                   const float* __restrict__ p0, const float* __restrict__ p1,
                   const float* __restrict__ p2, const float* __restrict__ p3,
                   float* __restrict__ out)
{
    constexpr int TM = 128, TN = 128;
    constexpr int ST = 36;                    // padded stride; rows 144B (16B-mult)
    __shared__ float sA[2][TM * ST];          // 2 x 18.4 KB
    __shared__ float sB[2][TN * ST];          // 2 x 18.4 KB

    const int c = blockIdx.z;
    const int count = g_count[c];
    const int m0 = blockIdx.x * TM;
    if (m0 >= count) return;
    const int n0 = blockIdx.y * TN;

    const float* emb  = (c == 0) ? e0 : (c == 1) ? e1 : (c == 2) ? e2 : e3;
    const float* proj = (c == 0) ? p0 : (c == 1) ? p1 : (c == 2) ? p2 : p3;
    const int K = (c == 0) ? 1024 : (c == 1) ? 256 : (c == 2) ? 64 : 16;
    const int nchunk = (K + 31) >> 5;

    const int tid = threadIdx.x;
    const int wid = tid >> 5;
    const int lid = tid & 31;
    const int wy = wid & 3;          // M warp coord (x32)
    const int wx = wid >> 2;         // N warp coord (x64)
    const int g   = lid >> 2;        // fragment groupID (0..7)
    const int tig = lid & 3;         // thread-in-group (0..3)

    // load slots: 128 rows x 8 float4 over 256 threads -> 4 slots (A and B alike)
    const int rowS = tid >> 3;       // +j*32
    const int kq   = tid & 7;
    int arow[4];
#pragma unroll
    for (int j = 0; j < 4; j++) {
        int m = rowS + j * 32;
        arow[j] = (m0 + m < count) ? g_row[c][m0 + m] : -1;
    }

    float acc[2][8][4];
#pragma unroll
    for (int mf = 0; mf < 2; mf++)
#pragma unroll
        for (int nf = 0; nf < 8; nf++)
#pragma unroll
            for (int q = 0; q < 4; q++) acc[mf][nf][q] = 0.0f;

    auto prefetch = [&](int ch, int stage) {
        const int k0 = ch << 5;
        const int kk = k0 + kq * 4;
#pragma unroll
        for (int j = 0; j < 4; j++) {
            int m = rowS + j * 32;
            uint32_t dst = (uint32_t)__cvta_generic_to_shared(&sA[stage][m * ST + kq * 4]);
            bool ok = (arow[j] >= 0) && (kk < K);
            const float* src = ok ? emb + (size_t)arow[j] * K + kk : emb;
            int vb = ok ? 16 : 0;
            asm volatile("cp.async.ca.shared.global [%0], [%1], 16, %2;"
                         :: "r"(dst), "l"(src), "r"(vb));
        }
#pragma unroll
        for (int j = 0; j < 4; j++) {
            int n = rowS + j * 32;
            uint32_t dst = (uint32_t)__cvta_generic_to_shared(&sB[stage][n * ST + kq * 4]);
            bool ok = (kk < K);
            const float* src = ok ? proj + (size_t)(n0 + n) * K + kk : proj;
            int vb = ok ? 16 : 0;
            asm volatile("cp.async.ca.shared.global [%0], [%1], 16, %2;"
                         :: "r"(dst), "l"(src), "r"(vb));
        }
        asm volatile("cp.async.commit_group;" ::: "memory");
    };

    prefetch(0, 0);

    for (int ch = 0; ch < nchunk; ch++) {
        const int buf = ch & 1;
        const bool more = (ch + 1) < nchunk;
        if (more) prefetch(ch + 1, buf ^ 1);

        if (more) asm volatile("cp.async.wait_group 1;" ::: "memory");
        else      asm volatile("cp.async.wait_group 0;" ::: "memory");
        __syncthreads();

        const float* cA = sA[buf];
        const float* cB = sB[buf];
#pragma unroll
        for (int ks = 0; ks < 4; ks++) {
            const int kk = ks * 8;
            uint32_t A[2][4], B[8][2];
#pragma unroll
            for (int mf = 0; mf < 2; mf++) {
                const float* ba = &cA[(wy * 32 + mf * 16 + g) * ST + kk + tig];
                A[mf][0] = f2tf32(ba[0]);
                A[mf][1] = f2tf32(ba[8 * ST]);
                A[mf][2] = f2tf32(ba[4]);
                A[mf][3] = f2tf32(ba[8 * ST + 4]);
            }
#pragma unroll
            for (int nf = 0; nf < 8; nf++) {
                const float* bb = &cB[(wx * 64 + nf * 8 + g) * ST + kk + tig];
                B[nf][0] = f2tf32(bb[0]);
                B[nf][1] = f2tf32(bb[4]);
            }
#pragma unroll
            for (int mf = 0; mf < 2; mf++)
#pragma unroll
                for (int nf = 0; nf < 8; nf++) {
                    asm volatile(
                        "mma.sync.aligned.m16n8k8.row.col.f32.tf32.tf32.f32 "
                        "{%0,%1,%2,%3}, {%4,%5,%6,%7}, {%8,%9}, {%0,%1,%2,%3};"
                        : "+f"(acc[mf][nf][0]), "+f"(acc[mf][nf][1]),
                          "+f"(acc[mf][nf][2]), "+f"(acc[mf][nf][3])
                        : "r"(A[mf][0]), "r"(A[mf][1]), "r"(A[mf][2]), "r"(A[mf][3]),
                          "r"(B[nf][0]), "r"(B[nf][1]));
                }
        }
        __syncthreads();
    }

    // ---- epilogue: c0,c1 at (row g, col 2*tig..+1); c2,c3 at row g+8
#pragma unroll
    for (int mf = 0; mf < 2; mf++) {
        int r0 = m0 + wy * 32 + mf * 16 + g;
        int r1 = r0 + 8;
        bool v0 = r0 < count, v1 = r1 < count;
        float* o0 = v0 ? out + (size_t)g_list[c][r0] * DPROJ + n0 : nullptr;
        float* o1 = v1 ? out + (size_t)g_list[c][r1] * DPROJ + n0 : nullptr;
#pragma unroll
        for (int nf = 0; nf < 8; nf++) {
            int col = wx * 64 + nf * 8 + 2 * tig;
            if (v0) {
                float2 w = make_float2(acc[mf][nf][0] * EMB_SCALE,
                                       acc[mf][nf][1] * EMB_SCALE);
                *(float2*)(o0 + col) = w;
            }
            if (v1) {
                float2 w = make_float2(acc[mf][nf][2] * EMB_SCALE,
                                       acc[mf][nf][3] * EMB_SCALE);
                *(float2*)(o1 + col) = w;
            }
        }
    }
}

// ---------------- host entry ----------------
extern "C" void kernel_launch(void* const* d_in, const int* in_sizes, int n_in,
                              void* d_out, int out_size) {
    // Map inputs by element count (robust to metadata ordering).
    const int* inp = (const int*)d_in[0];
    const float *emb[4] = {0, 0, 0, 0}, *proj[4] = {0, 0, 0, 0};
    for (int i = 1; i < n_in; i++) {
        long sz = in_sizes[i];
        const float* p = (const float*)d_in[i];
        switch (sz) {
            case 20000L * 1024:  emb[0]  = p; break;
            case 1024L * 1024:   proj[0] = p; break;
            case 20000L * 256:   emb[1]  = p; break;
            case 1024L * 256:    proj[1] = p; break;
            case 160000L * 64:   emb[2]  = p; break;
            case 1024L * 64:     proj[2] = p; break;
            case 67735L * 16:    emb[3]  = p; break;
            case 1024L * 16:     proj[3] = p; break;
            default: break;
        }
    }
    float* out = (float*)d_out;

    reset_kernel<<<1, 32>>>();
    partition_kernel<<<N_TOK_TOTAL / 256, 256>>>(inp);

    // worst-case grid: 128 m-tiles x 8 n-tiles x 4 clusters; early-exit
    dim3 grid(N_TOK_TOTAL / 128, DPROJ / 128, 4);
    fused_gemm_tc<<<grid, 256>>>(emb[0], emb[1], emb[2], emb[3],
                                 proj[0], proj[1], proj[2], proj[3], out);
}

// round 9
// speedup vs baseline: 1.2867x; 1.2867x over previous
#include <cuda_runtime.h>
#include <cuda_fp16.h>
#include <stdint.h>

#define N_TOK_TOTAL 16384
#define DPROJ 1024
#define EMB_SCALE 32.0f

// ---------------- device scratch (no allocations allowed) ----------------
__device__ int g_count[4];
__device__ int g_list[4][N_TOK_TOTAL];   // flat token index (output row)
__device__ int g_row[4][N_TOK_TOTAL];    // local embedding row

__global__ void reset_kernel() {
    if (threadIdx.x < 4) g_count[threadIdx.x] = 0;
}

__global__ void partition_kernel(const int* __restrict__ inp) {
    int t = blockIdx.x * blockDim.x + threadIdx.x;
    if (t >= N_TOK_TOTAL) return;
    int idx = inp[t];
    int c, l;
    if (idx < 20000)      { c = 0; l = 0; }
    else if (idx < 40000) { c = 1; l = 20000; }
    else if (idx < 200000){ c = 2; l = 40000; }
    else                  { c = 3; l = 200000; }
    int pos = atomicAdd(&g_count[c], 1);
    g_list[c][pos] = t;
    g_row[c][pos]  = idx - l;
}

// ---------------- fused fp16 mma.sync GEMM, double-buffered ----------------
// grid: (m-tile[128], n-tile[64], cluster). Early-exit on dynamic counts.
// D[m, n] = sum_k A[m, k] * B[n, k]; A = gathered emb rows, B = proj rows.
// 8 warps 4(M) x 2(N); warp tile 32x32 via m16n8k16 fp16 (fp32 accum).
// Pipeline per chunk: LDG(ch+1) -> ldmatrix+MMA(ch) -> cvt+STS(ch+1) -> sync.
// smem row = 32 halves data + pad = 80 B (5*16B): ldmatrix 8-row phases hit a
// bank-group permutation (5r mod 8) -> conflict-free.
__global__ __launch_bounds__(256, 2)
void fused_gemm_tc(const float* __restrict__ e0, const float* __restrict__ e1,
                   const float* __restrict__ e2, const float* __restrict__ e3,
                   const float* __restrict__ p0, const float* __restrict__ p1,
                   const float* __restrict__ p2, const float* __restrict__ p3,
                   float* __restrict__ out)
{
    constexpr int TM = 128, TN = 64;
    constexpr int STH = 40;                    // halves per row (80 B)
    __shared__ __half sA[2][TM * STH];         // 2 x 10 KB
    __shared__ __half sB[2][TN * STH];         // 2 x  5 KB

    const int c = blockIdx.z;
    const int count = g_count[c];
    const int m0 = blockIdx.x * TM;
    if (m0 >= count) return;
    const int n0 = blockIdx.y * TN;

    const float* emb  = (c == 0) ? e0 : (c == 1) ? e1 : (c == 2) ? e2 : e3;
    const float* proj = (c == 0) ? p0 : (c == 1) ? p1 : (c == 2) ? p2 : p3;
    const int K = (c == 0) ? 1024 : (c == 1) ? 256 : (c == 2) ? 64 : 16;
    const int nchunk = (K + 31) >> 5;

    const int tid = threadIdx.x;
    const int wid = tid >> 5;
    const int lid = tid & 31;
    const int wy = wid & 3;          // M warp coord (x32)
    const int wx = wid >> 2;         // N warp coord (x32)
    const int tig = lid & 3;         // thread-in-group (0..3)

    // producer slots: A: 128 rows x 8 float4 over 256 thr -> 4; B: 64 rows -> 2
    const int rowS = tid >> 3;
    const int kq   = tid & 7;
    int arow[4];
#pragma unroll
    for (int j = 0; j < 4; j++) {
        int m = rowS + j * 32;
        arow[j] = (m0 + m < count) ? g_row[c][m0 + m] : -1;
    }

    // ldmatrix per-lane byte offsets (row part): lanes 0-15 rows r0..r15 kg0,
    // lanes 16-31 same rows kg1 (+16B)
    const int lmRow = lid & 15;
    const int lmHi  = (lid >> 4) * 16;

    float acc[2][4][4];
#pragma unroll
    for (int mf = 0; mf < 2; mf++)
#pragma unroll
        for (int nf = 0; nf < 4; nf++)
#pragma unroll
            for (int q = 0; q < 4; q++) acc[mf][nf][q] = 0.0f;

    float4 av[4], bv[2];
    auto ldg_chunk = [&](int ch) {
        const int kk = (ch << 5) + kq * 4;
#pragma unroll
        for (int j = 0; j < 4; j++) {
            av[j] = make_float4(0.f, 0.f, 0.f, 0.f);
            if (arow[j] >= 0 && kk < K)
                av[j] = *(const float4*)(emb + (size_t)arow[j] * K + kk);
        }
#pragma unroll
        for (int j = 0; j < 2; j++) {
            bv[j] = make_float4(0.f, 0.f, 0.f, 0.f);
            if (kk < K)
                bv[j] = *(const float4*)(proj + (size_t)(n0 + rowS + j * 32) * K + kk);
        }
    };
    auto sts_chunk = [&](int stage) {
#pragma unroll
        for (int j = 0; j < 4; j++) {
            __half2 h01 = __floats2half2_rn(av[j].x, av[j].y);
            __half2 h23 = __floats2half2_rn(av[j].z, av[j].w);
            __half2* d = (__half2*)&sA[stage][(rowS + j * 32) * STH + kq * 4];
            d[0] = h01; d[1] = h23;
        }
#pragma unroll
        for (int j = 0; j < 2; j++) {
            __half2 h01 = __floats2half2_rn(bv[j].x, bv[j].y);
            __half2 h23 = __floats2half2_rn(bv[j].z, bv[j].w);
            __half2* d = (__half2*)&sB[stage][(rowS + j * 32) * STH + kq * 4];
            d[0] = h01; d[1] = h23;
        }
    };

    ldg_chunk(0);
    sts_chunk(0);
    __syncthreads();

    for (int ch = 0; ch < nchunk; ch++) {
        const int buf = ch & 1;
        const bool more = (ch + 1) < nchunk;
        if (more) ldg_chunk(ch + 1);

        const uint32_t baseA = (uint32_t)__cvta_generic_to_shared(sA[buf]);
        const uint32_t baseB = (uint32_t)__cvta_generic_to_shared(sB[buf]);
#pragma unroll
        for (int ks = 0; ks < 2; ks++) {
            uint32_t A[2][4], B[4][2];
#pragma unroll
            for (int mf = 0; mf < 2; mf++) {
                uint32_t addr = baseA + (uint32_t)((wy * 32 + mf * 16 + lmRow) * 80
                                                   + ks * 32 + lmHi);
                asm volatile("ldmatrix.sync.aligned.m8n8.x4.shared.b16 {%0,%1,%2,%3}, [%4];"
                             : "=r"(A[mf][0]), "=r"(A[mf][1]), "=r"(A[mf][2]), "=r"(A[mf][3])
                             : "r"(addr));
            }
#pragma unroll
            for (int nf2 = 0; nf2 < 2; nf2++) {
                uint32_t addr = baseB + (uint32_t)((wx * 32 + nf2 * 16 + lmRow) * 80
                                                   + ks * 32 + lmHi);
                uint32_t r0, r1, r2, r3;
                asm volatile("ldmatrix.sync.aligned.m8n8.x4.shared.b16 {%0,%1,%2,%3}, [%4];"
                             : "=r"(r0), "=r"(r1), "=r"(r2), "=r"(r3)
                             : "r"(addr));
                B[nf2 * 2 + 0][0] = r0;  B[nf2 * 2 + 1][0] = r1;
                B[nf2 * 2 + 0][1] = r2;  B[nf2 * 2 + 1][1] = r3;
            }
#pragma unroll
            for (int mf = 0; mf < 2; mf++)
#pragma unroll
                for (int nf = 0; nf < 4; nf++) {
                    asm volatile(
                        "mma.sync.aligned.m16n8k16.row.col.f32.f16.f16.f32 "
                        "{%0,%1,%2,%3}, {%4,%5,%6,%7}, {%8,%9}, {%0,%1,%2,%3};"
                        : "+f"(acc[mf][nf][0]), "+f"(acc[mf][nf][1]),
                          "+f"(acc[mf][nf][2]), "+f"(acc[mf][nf][3])
                        : "r"(A[mf][0]), "r"(A[mf][1]), "r"(A[mf][2]), "r"(A[mf][3]),
                          "r"(B[nf][0]), "r"(B[nf][1]));
                }
        }

        if (more) sts_chunk(buf ^ 1);
        __syncthreads();
    }

    // ---- epilogue: c0,c1 at (row g, col 2*tig..+1); c2,c3 at row g+8
    const int g = lid >> 2;
#pragma unroll
    for (int mf = 0; mf < 2; mf++) {
        int r0 = m0 + wy * 32 + mf * 16 + g;
        int r1 = r0 + 8;
        bool v0 = r0 < count, v1 = r1 < count;
        float* o0 = v0 ? out + (size_t)g_list[c][r0] * DPROJ + n0 : nullptr;
        float* o1 = v1 ? out + (size_t)g_list[c][r1] * DPROJ + n0 : nullptr;
#pragma unroll
        for (int nf = 0; nf < 4; nf++) {
            int col = wx * 32 + nf * 8 + 2 * tig;
            if (v0) {
                float2 w = make_float2(acc[mf][nf][0] * EMB_SCALE,
                                       acc[mf][nf][1] * EMB_SCALE);
                *(float2*)(o0 + col) = w;
            }
            if (v1) {
                float2 w = make_float2(acc[mf][nf][2] * EMB_SCALE,
                                       acc[mf][nf][3] * EMB_SCALE);
                *(float2*)(o1 + col) = w;
            }
        }
    }
}

// ---------------- host entry ----------------
extern "C" void kernel_launch(void* const* d_in, const int* in_sizes, int n_in,
                              void* d_out, int out_size) {
    // Map inputs by element count (robust to metadata ordering).
    const int* inp = (const int*)d_in[0];
    const float *emb[4] = {0, 0, 0, 0}, *proj[4] = {0, 0, 0, 0};
    for (int i = 1; i < n_in; i++) {
        long sz = in_sizes[i];
        const float* p = (const float*)d_in[i];
        switch (sz) {
            case 20000L * 1024:  emb[0]  = p; break;
            case 1024L * 1024:   proj[0] = p; break;
            case 20000L * 256:   emb[1]  = p; break;
            case 1024L * 256:    proj[1] = p; break;
            case 160000L * 64:   emb[2]  = p; break;
            case 1024L * 64:     proj[2] = p; break;
            case 67735L * 16:    emb[3]  = p; break;
            case 1024L * 16:     proj[3] = p; break;
            default: break;
        }
    }
    float* out = (float*)d_out;

    reset_kernel<<<1, 32>>>();
    partition_kernel<<<N_TOK_TOTAL / 256, 256>>>(inp);

    // worst-case grid: 128 m-tiles x 16 n-tiles x 4 clusters; early-exit
    dim3 grid(N_TOK_TOTAL / 128, DPROJ / 64, 4);
    fused_gemm_tc<<<grid, 256>>>(emb[0], emb[1], emb[2], emb[3],
                                 proj[0], proj[1], proj[2], proj[3], out);
}